// round 2
// baseline (speedup 1.0000x reference)
#include <cuda_runtime.h>
#include <math.h>

#define NB   2048   // batch
#define NH   512    // hidden
#define N4H  2048   // 4*hidden
#define NA   8      // act (output) dim
#define NZ   64     // z dim
#define NT   64     // seq_len
#define MR   16     // batch rows per CTA
#define TPB  256

// Scratch for the time-invariant input projection (B, 4H) fp32 = 16 MB
__device__ float g_xproj[NB * N4H];

// ---------------------------------------------------------------------------
// Kernel 1: x_proj[b, j] = sum_k z[b,k] * W_ih[j, 8+k] + b_ih[j] + b_hh[j]
// (dec_in = [zeros(B,8), z] -> first 8 columns of W_ih never contribute)
// Each block: 256 j-columns x 16 batch rows, W row cached in registers.
// ---------------------------------------------------------------------------
__global__ __launch_bounds__(256, 1)
void xproj_kernel(const float* __restrict__ z, const float* __restrict__ Wih,
                  const float* __restrict__ bih, const float* __restrict__ bhh)
{
    const int j  = blockIdx.x * 256 + threadIdx.x;
    const int b0 = blockIdx.y * 16;
    __shared__ float zs[16][64];
    for (int i = threadIdx.x; i < 16 * 64; i += 256)
        zs[i >> 6][i & 63] = z[(b0 + (i >> 6)) * NZ + (i & 63)];
    __syncthreads();

    float w[64];
#pragma unroll
    for (int k4 = 0; k4 < 16; k4++) {
        // (j*72 + 8)*4 bytes is 16B-aligned: 288*j + 32, 288 % 16 == 0
        float4 v = *(const float4*)&Wih[j * (NA + NZ) + NA + k4 * 4];
        w[k4*4+0] = v.x; w[k4*4+1] = v.y; w[k4*4+2] = v.z; w[k4*4+3] = v.w;
    }
    const float bias = bih[j] + bhh[j];
#pragma unroll
    for (int bb = 0; bb < 16; bb++) {
        float acc = bias;
#pragma unroll
        for (int k = 0; k < 64; k++) acc += zs[bb][k] * w[k];
        g_xproj[(b0 + bb) * N4H + j] = acc;
    }
}

__device__ __forceinline__ float sigf(float x) { return 1.0f / (1.0f + expf(-x)); }

// ---------------------------------------------------------------------------
// Kernel 2: the full 64-step LSTM + output projection.
// Grid: 128 CTAs, each owns 16 batch rows for all timesteps (rows of the
// recurrence are independent -> zero inter-CTA communication).
//
// Per step, per gate chunk (order i, g, f, o so state fits in registers):
//   gates[16 x 512] = x_proj + h[16 x 512] @ W_hh_chunk.T[512 x 512]
// W_hh tiles (16 k x 512 n) are LDG->reg-transpose->STS double-buffered.
// Thread (tm, tn): rows 4*tm..+3, cols {tn*4..+3} u {256+tn*4..+3}
// (split column pairs keep every LDS.128 / STS.128 bank-conflict-free).
// ---------------------------------------------------------------------------
__global__ __launch_bounds__(TPB, 1)
void lstm_kernel(const float* __restrict__ Whh, const float* __restrict__ Wout,
                 const float* __restrict__ bout, float* __restrict__ out)
{
    extern __shared__ float smem[];
    float* h_sh    = smem;                  // 16*512           = 8192 floats
    float* wtb     = smem + MR * NH;        // 2 * 16*512       = 16384 floats
    float* wout_sh = wtb + 2 * 16 * NH;     // 8 * 516 (padded) = 4128 floats

    const int tid   = threadIdx.x;
    const int tn    = tid & 63;
    const int tm    = tid >> 6;
    const int r0    = tm << 2;
    const int brow0 = blockIdx.x * MR;

    // init state + W_out staging
    for (int i = tid; i < MR * NH; i += TPB) h_sh[i] = 0.0f;
    for (int i = tid; i < NA * NH; i += TPB) wout_sh[(i >> 9) * 516 + (i & 511)] = Wout[i];
    float bo = 0.0f;
    const int om = tid >> 3, oa = tid & 7;
    if (tid < 128) bo = bout[oa];
    __syncthreads();

    // W_hh staging task decode: 512 (n4,k4) tasks over 2 passes x 256 threads.
    // n4 = lane&7 fastest -> conflict-free STS.128 after in-register 4x4 transpose.
    int n4_[2], k4_[2];
#pragma unroll
    for (int p = 0; p < 2; p++) {
        int idx = p * TPB + tid;
        n4_[p] = (idx & 7) + ((idx >> 5) << 3);
        k4_[p] = (idx >> 3) & 3;
    }

    float cst[4][8], ig[4][8];
#pragma unroll
    for (int r = 0; r < 4; r++)
#pragma unroll
        for (int jj = 0; jj < 8; jj++) { cst[r][jj] = 0.0f; ig[r][jj] = 0.0f; }

    float4 pre[2][4];  // LDG prefetch registers (next tile)

#define LDG_TILE(chunk, kt) { \
  _Pragma("unroll") \
  for (int p = 0; p < 2; p++) { \
    const float* gp = Whh + (((chunk) * 512 + n4_[p] * 4) * NH + (kt) * 16 + k4_[p] * 4); \
    _Pragma("unroll") \
    for (int r = 0; r < 4; r++) pre[p][r] = *(const float4*)(gp + r * NH); \
  } }

#define STS_TILE(buf) { \
  _Pragma("unroll") \
  for (int p = 0; p < 2; p++) { \
    float* sp = wtb + (buf) * (16 * NH) + (k4_[p] * 4) * NH + n4_[p] * 4; \
    *(float4*)(sp)        = make_float4(pre[p][0].x, pre[p][1].x, pre[p][2].x, pre[p][3].x); \
    *(float4*)(sp + NH)   = make_float4(pre[p][0].y, pre[p][1].y, pre[p][2].y, pre[p][3].y); \
    *(float4*)(sp + 2*NH) = make_float4(pre[p][0].z, pre[p][1].z, pre[p][2].z, pre[p][3].z); \
    *(float4*)(sp + 3*NH) = make_float4(pre[p][0].w, pre[p][1].w, pre[p][2].w, pre[p][3].w); \
  } }

#define COMP_TILE(buf, kt) { \
  const float* wbase = wtb + (buf) * (16 * NH); \
  _Pragma("unroll") \
  for (int k4i = 0; k4i < 4; k4i++) { \
    float hb[4][4]; \
    _Pragma("unroll") \
    for (int r = 0; r < 4; r++) { \
      float4 q = *(const float4*)&h_sh[(r0 + r) * NH + (kt) * 16 + k4i * 4]; \
      hb[r][0] = q.x; hb[r][1] = q.y; hb[r][2] = q.z; hb[r][3] = q.w; \
    } \
    _Pragma("unroll") \
    for (int kk = 0; kk < 4; kk++) { \
      const float* wr = wbase + (k4i * 4 + kk) * NH; \
      float4 wa  = *(const float4*)(wr + (tn << 2)); \
      float4 wb4 = *(const float4*)(wr + 256 + (tn << 2)); \
      float wv[8] = {wa.x, wa.y, wa.z, wa.w, wb4.x, wb4.y, wb4.z, wb4.w}; \
      _Pragma("unroll") \
      for (int r = 0; r < 4; r++) { \
        float hx = hb[r][kk]; \
        _Pragma("unroll") \
        for (int jj = 0; jj < 8; jj++) acc[r][jj] += hx * wv[jj]; \
      } \
    } \
  } }

    // initial prefetch: (t=0, chunk order index 0 -> chunk 0, kt=0)
    LDG_TILE(0, 0);

    for (int t = 0; t < NT; t++) {
#pragma unroll
        for (int ci = 0; ci < 4; ci++) {
            // gate chunk processing order: i(0), g(2), f(1), o(3)
            const int chunk = ((ci & 1) << 1) | (ci >> 1);

            float acc[4][8];
#pragma unroll
            for (int r = 0; r < 4; r++)
#pragma unroll
                for (int jj = 0; jj < 8; jj++) acc[r][jj] = 0.0f;

            for (int kt = 0; kt < 32; kt++) {
                const int buf = kt & 1;  // (t*128 + ci*32 + kt) & 1 == kt & 1
                STS_TILE(buf);
                int nkt = kt + 1, nci = ci;
                if (nkt == 32) { nkt = 0; nci = (ci + 1) & 3; }
                const int nchunk = ((nci & 1) << 1) | (nci >> 1);
                LDG_TILE(nchunk, nkt);   // prefetch next tile (wraps across step)
                __syncthreads();
                COMP_TILE(buf, kt);
                __syncthreads();
            }

            // epilogue: add x_proj, apply gate nonlinearity, update state
#pragma unroll
            for (int r = 0; r < 4; r++) {
                const float* xg = g_xproj + (size_t)(brow0 + r0 + r) * N4H + chunk * 512;
                float4 a = *(const float4*)(xg + (tn << 2));
                float4 b = *(const float4*)(xg + 256 + (tn << 2));
                float xv[8] = {a.x, a.y, a.z, a.w, b.x, b.y, b.z, b.w};
#pragma unroll
                for (int jj = 0; jj < 8; jj++) {
                    float v = acc[r][jj] + xv[jj];
                    if (chunk == 0)       ig[r][jj]  = sigf(v);                         // i
                    else if (chunk == 2)  ig[r][jj] *= tanhf(v);                        // * g
                    else if (chunk == 1)  cst[r][jj] = sigf(v) * cst[r][jj] + ig[r][jj];// c
                    else                  ig[r][jj]  = sigf(v) * tanhf(cst[r][jj]);     // h (o)
                }
            }

            if (chunk == 3) {
                // all reads of old h finished at the last tile's trailing barrier
#pragma unroll
                for (int r = 0; r < 4; r++) {
                    *(float4*)&h_sh[(r0 + r) * NH + (tn << 2)] =
                        make_float4(ig[r][0], ig[r][1], ig[r][2], ig[r][3]);
                    *(float4*)&h_sh[(r0 + r) * NH + 256 + (tn << 2)] =
                        make_float4(ig[r][4], ig[r][5], ig[r][6], ig[r][7]);
                }
                __syncthreads();
                // fused output projection: out[b, t, :] = h @ W_out.T + b_out
                if (tid < 128) {
                    float s0 = 0.f, s1 = 0.f, s2 = 0.f, s3 = 0.f;
                    const float* hp = h_sh + om * NH;
                    const float* wp = wout_sh + oa * 516;
#pragma unroll 8
                    for (int u4 = 0; u4 < 128; u4++) {
                        float4 hq = *(const float4*)(hp + (u4 << 2));
                        float4 wq = *(const float4*)(wp + (u4 << 2));
                        s0 += hq.x * wq.x; s1 += hq.y * wq.y;
                        s2 += hq.z * wq.z; s3 += hq.w * wq.w;
                    }
                    out[((brow0 + om) * NT + t) * NA + oa] = s0 + s1 + s2 + s3 + bo;
                }
            }
        }
    }
#undef LDG_TILE
#undef STS_TILE
#undef COMP_TILE
}

// ---------------------------------------------------------------------------
// Inputs (metadata order): z, W_ih, W_hh, b_ih, b_hh, W_out, b_out, seq_len
// ---------------------------------------------------------------------------
extern "C" void kernel_launch(void* const* d_in, const int* in_sizes, int n_in,
                              void* d_out, int out_size)
{
    (void)in_sizes; (void)n_in; (void)out_size;
    const float* z    = (const float*)d_in[0];
    const float* Wih  = (const float*)d_in[1];
    const float* Whh  = (const float*)d_in[2];
    const float* bih  = (const float*)d_in[3];
    const float* bhh  = (const float*)d_in[4];
    const float* Wout = (const float*)d_in[5];
    const float* bout = (const float*)d_in[6];
    float* out = (float*)d_out;

    xproj_kernel<<<dim3(N4H / 256, NB / 16), 256>>>(z, Wih, bih, bhh);

    const size_t smem_bytes = (size_t)(MR * NH + 2 * 16 * NH + NA * 516) * sizeof(float);
    cudaFuncSetAttribute(lstm_kernel, cudaFuncAttributeMaxDynamicSharedMemorySize,
                         (int)smem_bytes);
    lstm_kernel<<<NB / MR, TPB, smem_bytes>>>(Whh, Wout, bout, out);
}

// round 3
// speedup vs baseline: 1.0018x; 1.0018x over previous
#include <cuda_runtime.h>
#include <math.h>

#define NB   2048   // batch
#define NH   512    // hidden
#define N4H  2048   // 4*hidden
#define NA   8      // act (output) dim
#define NZ   64     // z dim
#define NT   64     // seq_len
#define MR   16     // batch rows per CTA
#define TPB  256

// Scratch for the time-invariant input projection (B, 4H) fp32 = 16 MB
__device__ float g_xproj[NB * N4H];

// ---------------------------------------------------------------------------
// Kernel 1: x_proj[b, j] = sum_k z[b,k] * W_ih[j, 8+k] + b_ih[j] + b_hh[j]
// (dec_in = [zeros(B,8), z] -> first 8 columns of W_ih never contribute)
// Each block: 256 j-columns x 16 batch rows, W row cached in registers.
// ---------------------------------------------------------------------------
__global__ __launch_bounds__(256, 1)
void xproj_kernel(const float* __restrict__ z, const float* __restrict__ Wih,
                  const float* __restrict__ bih, const float* __restrict__ bhh)
{
    const int j  = blockIdx.x * 256 + threadIdx.x;
    const int b0 = blockIdx.y * 16;
    __shared__ float zs[16][64];
    for (int i = threadIdx.x; i < 16 * 64; i += 256)
        zs[i >> 6][i & 63] = z[(b0 + (i >> 6)) * NZ + (i & 63)];
    __syncthreads();

    float w[64];
#pragma unroll
    for (int k4 = 0; k4 < 16; k4++) {
        // (j*72 + 8)*4 bytes is 16B-aligned: 288*j + 32, 288 % 16 == 0
        float4 v = *(const float4*)&Wih[j * (NA + NZ) + NA + k4 * 4];
        w[k4*4+0] = v.x; w[k4*4+1] = v.y; w[k4*4+2] = v.z; w[k4*4+3] = v.w;
    }
    const float bias = bih[j] + bhh[j];
#pragma unroll
    for (int bb = 0; bb < 16; bb++) {
        float acc = bias;
#pragma unroll
        for (int k = 0; k < 64; k++) acc += zs[bb][k] * w[k];
        g_xproj[(b0 + bb) * N4H + j] = acc;
    }
}

__device__ __forceinline__ float sigf(float x) { return 1.0f / (1.0f + expf(-x)); }

// ---------------------------------------------------------------------------
// Kernel 2: the full 64-step LSTM + output projection.
// Grid: 128 CTAs, each owns 16 batch rows for all timesteps (rows of the
// recurrence are independent -> zero inter-CTA communication).
//
// Per step, per gate chunk (order i, g, f, o so state fits in registers):
//   gates[16 x 512] = x_proj + h[16 x 512] @ W_hh_chunk.T[512 x 512]
// W_hh tiles (16 k x 512 n) are LDG->reg-transpose->STS double-buffered.
// Thread (tm, tn): rows 4*tm..+3, cols {tn*4..+3} u {256+tn*4..+3}
// (split column pairs keep every LDS.128 / STS.128 bank-conflict-free).
// ---------------------------------------------------------------------------
__global__ __launch_bounds__(TPB, 1)
void lstm_kernel(const float* __restrict__ Whh, const float* __restrict__ Wout,
                 const float* __restrict__ bout, float* __restrict__ out)
{
    extern __shared__ float smem[];
    float* h_sh    = smem;                  // 16*512           = 8192 floats
    float* wtb     = smem + MR * NH;        // 2 * 16*512       = 16384 floats
    float* wout_sh = wtb + 2 * 16 * NH;     // 8 * 516 (padded) = 4128 floats

    const int tid   = threadIdx.x;
    const int tn    = tid & 63;
    const int tm    = tid >> 6;
    const int r0    = tm << 2;
    const int brow0 = blockIdx.x * MR;

    // init state + W_out staging
    for (int i = tid; i < MR * NH; i += TPB) h_sh[i] = 0.0f;
    for (int i = tid; i < NA * NH; i += TPB) wout_sh[(i >> 9) * 516 + (i & 511)] = Wout[i];
    float bo = 0.0f;
    const int om = tid >> 3, oa = tid & 7;
    if (tid < 128) bo = bout[oa];
    __syncthreads();

    // W_hh staging task decode: 512 (n4,k4) tasks over 2 passes x 256 threads.
    // n4 = lane&7 fastest -> conflict-free STS.128 after in-register 4x4 transpose.
    int n4_[2], k4_[2];
#pragma unroll
    for (int p = 0; p < 2; p++) {
        int idx = p * TPB + tid;
        n4_[p] = (idx & 7) + ((idx >> 5) << 3);
        k4_[p] = (idx >> 3) & 3;
    }

    float cst[4][8], ig[4][8];
#pragma unroll
    for (int r = 0; r < 4; r++)
#pragma unroll
        for (int jj = 0; jj < 8; jj++) { cst[r][jj] = 0.0f; ig[r][jj] = 0.0f; }

    float4 pre[2][4];  // LDG prefetch registers (next tile)

#define LDG_TILE(chunk, kt) { \
  _Pragma("unroll") \
  for (int p = 0; p < 2; p++) { \
    const float* gp = Whh + (((chunk) * 512 + n4_[p] * 4) * NH + (kt) * 16 + k4_[p] * 4); \
    _Pragma("unroll") \
    for (int r = 0; r < 4; r++) pre[p][r] = *(const float4*)(gp + r * NH); \
  } }

#define STS_TILE(buf) { \
  _Pragma("unroll") \
  for (int p = 0; p < 2; p++) { \
    float* sp = wtb + (buf) * (16 * NH) + (k4_[p] * 4) * NH + n4_[p] * 4; \
    *(float4*)(sp)        = make_float4(pre[p][0].x, pre[p][1].x, pre[p][2].x, pre[p][3].x); \
    *(float4*)(sp + NH)   = make_float4(pre[p][0].y, pre[p][1].y, pre[p][2].y, pre[p][3].y); \
    *(float4*)(sp + 2*NH) = make_float4(pre[p][0].z, pre[p][1].z, pre[p][2].z, pre[p][3].z); \
    *(float4*)(sp + 3*NH) = make_float4(pre[p][0].w, pre[p][1].w, pre[p][2].w, pre[p][3].w); \
  } }

#define COMP_TILE(buf, kt) { \
  const float* wbase = wtb + (buf) * (16 * NH); \
  _Pragma("unroll") \
  for (int k4i = 0; k4i < 4; k4i++) { \
    float hb[4][4]; \
    _Pragma("unroll") \
    for (int r = 0; r < 4; r++) { \
      float4 q = *(const float4*)&h_sh[(r0 + r) * NH + (kt) * 16 + k4i * 4]; \
      hb[r][0] = q.x; hb[r][1] = q.y; hb[r][2] = q.z; hb[r][3] = q.w; \
    } \
    _Pragma("unroll") \
    for (int kk = 0; kk < 4; kk++) { \
      const float* wr = wbase + (k4i * 4 + kk) * NH; \
      float4 wa  = *(const float4*)(wr + (tn << 2)); \
      float4 wb4 = *(const float4*)(wr + 256 + (tn << 2)); \
      float wv[8] = {wa.x, wa.y, wa.z, wa.w, wb4.x, wb4.y, wb4.z, wb4.w}; \
      _Pragma("unroll") \
      for (int r = 0; r < 4; r++) { \
        float hx = hb[r][kk]; \
        _Pragma("unroll") \
        for (int jj = 0; jj < 8; jj++) acc[r][jj] += hx * wv[jj]; \
      } \
    } \
  } }

    // initial prefetch: (t=0, chunk order index 0 -> chunk 0, kt=0)
    LDG_TILE(0, 0);

    for (int t = 0; t < NT; t++) {
#pragma unroll
        for (int ci = 0; ci < 4; ci++) {
            // gate chunk processing order: i(0), g(2), f(1), o(3)
            const int chunk = ((ci & 1) << 1) | (ci >> 1);

            float acc[4][8];
#pragma unroll
            for (int r = 0; r < 4; r++)
#pragma unroll
                for (int jj = 0; jj < 8; jj++) acc[r][jj] = 0.0f;

            for (int kt = 0; kt < 32; kt++) {
                const int buf = kt & 1;  // (t*128 + ci*32 + kt) & 1 == kt & 1
                STS_TILE(buf);
                int nkt = kt + 1, nci = ci;
                if (nkt == 32) { nkt = 0; nci = (ci + 1) & 3; }
                const int nchunk = ((nci & 1) << 1) | (nci >> 1);
                LDG_TILE(nchunk, nkt);   // prefetch next tile (wraps across step)
                __syncthreads();
                COMP_TILE(buf, kt);
                __syncthreads();
            }

            // epilogue: add x_proj, apply gate nonlinearity, update state
#pragma unroll
            for (int r = 0; r < 4; r++) {
                const float* xg = g_xproj + (size_t)(brow0 + r0 + r) * N4H + chunk * 512;
                float4 a = *(const float4*)(xg + (tn << 2));
                float4 b = *(const float4*)(xg + 256 + (tn << 2));
                float xv[8] = {a.x, a.y, a.z, a.w, b.x, b.y, b.z, b.w};
#pragma unroll
                for (int jj = 0; jj < 8; jj++) {
                    float v = acc[r][jj] + xv[jj];
                    if (chunk == 0)       ig[r][jj]  = sigf(v);                         // i
                    else if (chunk == 2)  ig[r][jj] *= tanhf(v);                        // * g
                    else if (chunk == 1)  cst[r][jj] = sigf(v) * cst[r][jj] + ig[r][jj];// c
                    else                  ig[r][jj]  = sigf(v) * tanhf(cst[r][jj]);     // h (o)
                }
            }

            if (chunk == 3) {
                // all reads of old h finished at the last tile's trailing barrier
#pragma unroll
                for (int r = 0; r < 4; r++) {
                    *(float4*)&h_sh[(r0 + r) * NH + (tn << 2)] =
                        make_float4(ig[r][0], ig[r][1], ig[r][2], ig[r][3]);
                    *(float4*)&h_sh[(r0 + r) * NH + 256 + (tn << 2)] =
                        make_float4(ig[r][4], ig[r][5], ig[r][6], ig[r][7]);
                }
                __syncthreads();
                // fused output projection: out[b, t, :] = h @ W_out.T + b_out
                if (tid < 128) {
                    float s0 = 0.f, s1 = 0.f, s2 = 0.f, s3 = 0.f;
                    const float* hp = h_sh + om * NH;
                    const float* wp = wout_sh + oa * 516;
#pragma unroll 8
                    for (int u4 = 0; u4 < 128; u4++) {
                        float4 hq = *(const float4*)(hp + (u4 << 2));
                        float4 wq = *(const float4*)(wp + (u4 << 2));
                        s0 += hq.x * wq.x; s1 += hq.y * wq.y;
                        s2 += hq.z * wq.z; s3 += hq.w * wq.w;
                    }
                    out[((brow0 + om) * NT + t) * NA + oa] = s0 + s1 + s2 + s3 + bo;
                }
            }
        }
    }
#undef LDG_TILE
#undef STS_TILE
#undef COMP_TILE
}

// ---------------------------------------------------------------------------
// Inputs (metadata order): z, W_ih, W_hh, b_ih, b_hh, W_out, b_out, seq_len
// ---------------------------------------------------------------------------
extern "C" void kernel_launch(void* const* d_in, const int* in_sizes, int n_in,
                              void* d_out, int out_size)
{
    (void)in_sizes; (void)n_in; (void)out_size;
    const float* z    = (const float*)d_in[0];
    const float* Wih  = (const float*)d_in[1];
    const float* Whh  = (const float*)d_in[2];
    const float* bih  = (const float*)d_in[3];
    const float* bhh  = (const float*)d_in[4];
    const float* Wout = (const float*)d_in[5];
    const float* bout = (const float*)d_in[6];
    float* out = (float*)d_out;

    xproj_kernel<<<dim3(N4H / 256, NB / 16), 256>>>(z, Wih, bih, bhh);

    const size_t smem_bytes = (size_t)(MR * NH + 2 * 16 * NH + NA * 516) * sizeof(float);
    cudaFuncSetAttribute(lstm_kernel, cudaFuncAttributeMaxDynamicSharedMemorySize,
                         (int)smem_bytes);
    lstm_kernel<<<NB / MR, TPB, smem_bytes>>>(Whh, Wout, bout, out);
}

// round 5
// speedup vs baseline: 3.0753x; 3.0697x over previous
#include <cuda_runtime.h>
#include <cuda_bf16.h>
#include <cstdint>
#include <math.h>

#define NB   2048
#define NH   512
#define N4H  2048
#define NA   8
#define NZ   64
#define NT   64
#define TPB  256

// staging: per stage  A_hi 16K | A_lo 16K | B_hi 32K | B_lo 32K = 96KB, x2
#define SA_AH 0
#define SA_AL 16384
#define SA_BH 32768
#define SA_BL 65536
#define STAGE_SZ  98304
#define SMEM_TOTAL (2 * STAGE_SZ)    // 196608

#define SWZ(o) ((o) ^ ((((unsigned)(o)) >> 3) & 0x70))

// ---- device scratch (static allocation is allowed) ----
__device__ float          g_xproj[NB * N4H];        // (b, 4H) fp32
__device__ __nv_bfloat16  g_WbH[N4H * NH];          // permuted rows, hi
__device__ __nv_bfloat16  g_WbL[N4H * NH];          // lo
__device__ __nv_bfloat16  g_hbH[2][NB * NH];        // h hi ping-pong
__device__ __nv_bfloat16  g_hbL[2][NB * NH];        // h lo ping-pong
__device__ float          g_hist[(size_t)NT * NB * NH];  // fp32 h history, 256MB

// ================= PTX helpers =================
__device__ __forceinline__ uint32_t smem_u32(const void* p) {
    uint32_t a;
    asm("{ .reg .u64 t; cvta.to.shared.u64 t, %1; cvt.u32.u64 %0, t; }" : "=r"(a) : "l"(p));
    return a;
}
__device__ __forceinline__ void cp16(uint32_t dst, const void* src) {
    asm volatile("cp.async.cg.shared.global [%0], [%1], 16;" :: "r"(dst), "l"(src) : "memory");
}
#define CP_COMMIT() asm volatile("cp.async.commit_group;" ::: "memory")
#define CP_WAIT1()  asm volatile("cp.async.wait_group 1;"  ::: "memory")
#define CP_WAIT0()  asm volatile("cp.async.wait_group 0;"  ::: "memory")
#define CLUSTER_SYNC() do { \
    asm volatile("barrier.cluster.arrive.aligned;" ::: "memory"); \
    asm volatile("barrier.cluster.wait.aligned;"   ::: "memory"); } while (0)

#define LDM_X4(r, ad) \
    asm volatile("ldmatrix.sync.aligned.m8n8.x4.shared.b16 {%0,%1,%2,%3}, [%4];" \
        : "=r"((r)[0]), "=r"((r)[1]), "=r"((r)[2]), "=r"((r)[3]) : "r"(ad))

#define MMA_BF16(d, a, b0, b1) \
    asm volatile("mma.sync.aligned.m16n8k16.row.col.f32.bf16.bf16.f32 " \
        "{%0,%1,%2,%3}, {%4,%5,%6,%7}, {%8,%9}, {%0,%1,%2,%3};" \
        : "+f"((d)[0]), "+f"((d)[1]), "+f"((d)[2]), "+f"((d)[3]) \
        : "r"((a)[0]), "r"((a)[1]), "r"((a)[2]), "r"((a)[3]), "r"(b0), "r"(b1))

__device__ __forceinline__ float sigx(float x)  { return __fdividef(1.0f, 1.0f + __expf(-x)); }
__device__ __forceinline__ float tanhx(float x) { return __fdividef(2.0f, 1.0f + __expf(-2.0f * x)) - 1.0f; }

__device__ __forceinline__ uint32_t pack_bf2(float a, float b) {
    __nv_bfloat162 t = __floats2bfloat162_rn(a, b);   // low = a, high = b
    return *(uint32_t*)&t;
}

// ================= prep kernels =================
__global__ __launch_bounds__(256, 1)
void xproj_kernel(const float* __restrict__ z, const float* __restrict__ Wih,
                  const float* __restrict__ bih, const float* __restrict__ bhh)
{
    const int j  = blockIdx.x * 256 + threadIdx.x;
    const int b0 = blockIdx.y * 16;
    __shared__ float zs[16][64];
    for (int i = threadIdx.x; i < 16 * 64; i += 256)
        zs[i >> 6][i & 63] = z[(b0 + (i >> 6)) * NZ + (i & 63)];
    __syncthreads();
    float w[64];
#pragma unroll
    for (int k4 = 0; k4 < 16; k4++) {
        float4 v = *(const float4*)&Wih[j * (NA + NZ) + NA + k4 * 4];
        w[k4*4+0] = v.x; w[k4*4+1] = v.y; w[k4*4+2] = v.z; w[k4*4+3] = v.w;
    }
    const float bias = bih[j] + bhh[j];
#pragma unroll
    for (int bb = 0; bb < 16; bb++) {
        float acc = bias;
#pragma unroll
        for (int k = 0; k < 64; k++) acc += zs[bb][k] * w[k];
        g_xproj[(size_t)(b0 + bb) * N4H + j] = acc;
    }
}

// W split with row permutation: p = rank*256 + gate*64 + jj  <->  orig gate*512 + rank*64 + jj
__global__ __launch_bounds__(256, 1)
void wsplit_kernel(const float* __restrict__ Whh)
{
    const int g = blockIdx.x * 256 + threadIdx.x;   // 0 .. 1M-1
    const int p = g >> 9, k = g & 511;
    const int orow = ((p >> 6) & 3) * 512 + (p >> 8) * 64 + (p & 63);
    float w = Whh[(size_t)orow * NH + k];
    __nv_bfloat16 hi = __float2bfloat16(w);
    __nv_bfloat16 lo = __float2bfloat16(w - __bfloat162float(hi));
    g_WbH[g] = hi; g_WbL[g] = lo;
}

__global__ __launch_bounds__(256, 1)
void zeroh_kernel()
{
    const int i = blockIdx.x * 256 + threadIdx.x;   // 512K u32 each
    ((uint32_t*)&g_hbH[0][0])[i] = 0;
    ((uint32_t*)&g_hbL[0][0])[i] = 0;
}

// out[b][t][a] = hist[t][b][:] . Wout[a][:] + bout[a]
__global__ __launch_bounds__(128, 1)
void outproj_kernel(const float* __restrict__ Wout, const float* __restrict__ bout,
                    float* __restrict__ out)
{
    __shared__ float hs[16][516];
    const int tid = threadIdx.x;
    const size_t r0 = (size_t)blockIdx.x * 16;
    const float4* src = (const float4*)&g_hist[r0 * NH];
    for (int i = tid; i < 16 * 128; i += 128) {
        float4 v = src[i];
        *(float4*)&hs[i >> 7][(i & 127) * 4] = v;
    }
    __syncthreads();
    const int r = tid >> 3, a = tid & 7;
    float s = bout[a];
    const float* hp = hs[r];
#pragma unroll 4
    for (int u4 = 0; u4 < 128; u4++) {
        float4 wq = __ldg((const float4*)&Wout[a * NH + u4 * 4]);
        float4 hq = *(const float4*)&hp[u4 * 4];
        s += hq.x * wq.x + hq.y * wq.y + hq.z * wq.z + hq.w * wq.w;
    }
    const size_t row = r0 + r;
    const int t = (int)(row >> 11), b = (int)(row & 2047);
    out[((size_t)b * NT + t) * NA + a] = s;
}

// ================= main LSTM kernel (warp-level bf16 MMA) =================
extern __shared__ char dsm[];

__global__ __launch_bounds__(TPB, 1) __cluster_dims__(8, 1, 1)
void lstm_mma_kernel()
{
    const uint32_t sb = smem_u32(dsm);
    const int tid  = threadIdx.x;
    const int lane = tid & 31;
    const int wid  = tid >> 5;
    const int wm   = wid & 1;          // M half (64 rows)
    const int u0w  = (wid >> 1) * 16;  // u-block of 16 hidden units
    const int rank  = blockIdx.x & 7;
    const int brow0 = (blockIdx.x >> 3) * 128;

    // per-thread fragment coordinates
    const int frow = (lane >> 2);          // + eh*8
    const int fcol = (lane & 3) * 2;       // + parity

    float acc[4][8][4];   // [m-tile][gate*2+u8][e]
    float cst[4][2][4];   // cell state [m-tile][u8][e]
#pragma unroll
    for (int i = 0; i < 4; i++)
#pragma unroll
        for (int u8 = 0; u8 < 2; u8++)
#pragma unroll
            for (int e = 0; e < 4; e++) cst[i][u8][e] = 0.0f;

    const char* Wbase_H = (const char*)g_WbH + (size_t)rank * 256 * 1024;
    const char* Wbase_L = (const char*)g_WbL + (size_t)rank * 256 * 1024;

    for (int t = 0; t < NT; t++) {
        const int hb = t & 1, nb = hb ^ 1;
        const char* A_H = (const char*)g_hbH[hb] + (size_t)brow0 * 1024;
        const char* A_L = (const char*)g_hbL[hb] + (size_t)brow0 * 1024;

#define LOAD_CHUNK(kc, sbuf) { \
    const uint32_t stg = sb + (sbuf) * STAGE_SZ; \
    _Pragma("unroll") \
    for (int i = 0; i < 4; i++) { \
        int q = tid + i * 256, row = q >> 3, c16 = (q & 7) * 16; \
        uint32_t sw = SWZ(row * 128 + c16); \
        size_t so = (size_t)row * 1024 + (kc) * 128 + c16; \
        cp16(stg + SA_AH + sw, A_H + so); \
        cp16(stg + SA_AL + sw, A_L + so); \
    } \
    _Pragma("unroll") \
    for (int i = 0; i < 8; i++) { \
        int q = tid + i * 256, row = q >> 3, c16 = (q & 7) * 16; \
        uint32_t sw = SWZ(row * 128 + c16); \
        size_t so = (size_t)row * 1024 + (kc) * 128 + c16; \
        cp16(stg + SA_BH + sw, Wbase_H + so); \
        cp16(stg + SA_BL + sw, Wbase_L + so); \
    } }

        // issue chunk 0 loads, then init accumulators with x_proj (overlaps latency)
        LOAD_CHUNK(0, 0);
        CP_COMMIT();
#pragma unroll
        for (int i = 0; i < 4; i++)
#pragma unroll
            for (int eh = 0; eh < 2; eh++) {
                const int b = brow0 + wm * 64 + i * 16 + frow + eh * 8;
                const float* xrow = g_xproj + (size_t)b * N4H + rank * 64 + u0w + fcol;
#pragma unroll
                for (int g = 0; g < 4; g++)
#pragma unroll
                    for (int u8 = 0; u8 < 2; u8++) {
                        float2 v = __ldg((const float2*)(xrow + g * 512 + u8 * 8));
                        acc[i][g * 2 + u8][eh * 2 + 0] = v.x;
                        acc[i][g * 2 + u8][eh * 2 + 1] = v.y;
                    }
            }

        // ---- K pipeline: 8 chunks of 64, double buffered ----
        for (int kc = 0; kc < 8; kc++) {
            if (kc < 7) { LOAD_CHUNK(kc + 1, (kc + 1) & 1); CP_COMMIT(); }
            if (kc < 7) CP_WAIT1(); else CP_WAIT0();
            __syncthreads();

            const uint32_t stg = sb + (kc & 1) * STAGE_SZ;
#pragma unroll
            for (int s = 0; s < 4; s++) {
                uint32_t Ah[4][4], Al[4][4];
#pragma unroll
                for (int i = 0; i < 4; i++) {
                    const int row = wm * 64 + i * 16 + (lane & 15);
                    const int kb  = s * 32 + ((lane >> 4) << 4);
                    const uint32_t sw = SWZ(row * 128 + kb);
                    LDM_X4(Ah[i], stg + SA_AH + sw);
                    LDM_X4(Al[i], stg + SA_AL + sw);
                }
#pragma unroll
                for (int g = 0; g < 4; g++) {
                    uint32_t Bh[4], Bl[4];
                    const int n  = g * 64 + u0w + ((lane >> 4) << 3) + (lane & 7);
                    const int kb = s * 32 + (((lane >> 3) & 1) << 4);
                    const uint32_t sw = SWZ(n * 128 + kb);
                    LDM_X4(Bh, stg + SA_BH + sw);
                    LDM_X4(Bl, stg + SA_BL + sw);
#pragma unroll
                    for (int i = 0; i < 4; i++) {
                        MMA_BF16(acc[i][g * 2 + 0], Ah[i], Bh[0], Bh[1]);
                        MMA_BF16(acc[i][g * 2 + 1], Ah[i], Bh[2], Bh[3]);
                        MMA_BF16(acc[i][g * 2 + 0], Al[i], Bh[0], Bh[1]);
                        MMA_BF16(acc[i][g * 2 + 1], Al[i], Bh[2], Bh[3]);
                        MMA_BF16(acc[i][g * 2 + 0], Ah[i], Bl[0], Bl[1]);
                        MMA_BF16(acc[i][g * 2 + 1], Ah[i], Bl[2], Bl[3]);
                    }
                }
            }
            __syncthreads();
        }
#undef LOAD_CHUNK

        // ---- epilogue: gates -> c,h ; write h (bf16 hi/lo ping-pong + fp32 history)
#pragma unroll
        for (int i = 0; i < 4; i++)
#pragma unroll
            for (int eh = 0; eh < 2; eh++) {
                const int b = brow0 + wm * 64 + i * 16 + frow + eh * 8;
                const int U = rank * 64 + u0w + fcol;   // + u8*8, even
#pragma unroll
                for (int u8 = 0; u8 < 2; u8++) {
                    float h2[2];
#pragma unroll
                    for (int p = 0; p < 2; p++) {
                        const int e = eh * 2 + p;
                        float iv = sigx (acc[i][0 + u8][e]);
                        float fv = sigx (acc[i][2 + u8][e]);
                        float gv = tanhx(acc[i][4 + u8][e]);
                        float ov = sigx (acc[i][6 + u8][e]);
                        float cc = fv * cst[i][u8][e] + iv * gv;
                        cst[i][u8][e] = cc;
                        h2[p] = ov * tanhx(cc);
                    }
                    const int Uu = U + u8 * 8;
                    *(float2*)&g_hist[((size_t)t * NB + b) * NH + Uu] =
                        make_float2(h2[0], h2[1]);
                    __nv_bfloat16 h0h = __float2bfloat16(h2[0]);
                    __nv_bfloat16 h1h = __float2bfloat16(h2[1]);
                    float l0 = h2[0] - __bfloat162float(h0h);
                    float l1 = h2[1] - __bfloat162float(h1h);
                    *(uint32_t*)((char*)g_hbH[nb] + (size_t)b * 1024 + Uu * 2) =
                        pack_bf2(h2[0], h2[1]);
                    *(uint32_t*)((char*)g_hbL[nb] + (size_t)b * 1024 + Uu * 2) =
                        pack_bf2(l0, l1);
                }
            }

        __threadfence();
        CLUSTER_SYNC();   // h(t+1) visible to all ranks of this cluster
    }
}

// ---------------------------------------------------------------------------
// Inputs: z, W_ih, W_hh, b_ih, b_hh, W_out, b_out, seq_len
// ---------------------------------------------------------------------------
extern "C" void kernel_launch(void* const* d_in, const int* in_sizes, int n_in,
                              void* d_out, int out_size)
{
    (void)in_sizes; (void)n_in; (void)out_size;
    const float* z    = (const float*)d_in[0];
    const float* Wih  = (const float*)d_in[1];
    const float* Whh  = (const float*)d_in[2];
    const float* bih  = (const float*)d_in[3];
    const float* bhh  = (const float*)d_in[4];
    const float* Wout = (const float*)d_in[5];
    const float* bout = (const float*)d_in[6];
    float* out = (float*)d_out;

    zeroh_kernel <<<2048, 256>>>();
    xproj_kernel <<<dim3(N4H / 256, NB / 16), 256>>>(z, Wih, bih, bhh);
    wsplit_kernel<<<(N4H * NH) / 256, 256>>>(Whh);

    cudaFuncSetAttribute(lstm_mma_kernel, cudaFuncAttributeMaxDynamicSharedMemorySize,
                         SMEM_TOTAL);
    lstm_mma_kernel<<<128, TPB, SMEM_TOTAL>>>();

    outproj_kernel<<<(NT * NB) / 16, 128>>>(Wout, bout, out);
}